// round 3
// baseline (speedup 1.0000x reference)
#include <cuda_runtime.h>
#include <math.h>

// Fused LogEig -> MaxPool(4,2) -> ExpEig for batched 32x32 SPD matrices.
//
// LogEig: degree-15 Chebyshev expansion of log on [0.98, 8.0], evaluated with
// the Clenshaw recurrence  b_k = c_k I + 2 Y b_{k+1} - b_{k+2},
// f = c0 I + Y b_1 - b_2.  (lambda(x) in [1, ~5.8] provably, huge margin.)
// ExpEig: scaling-and-squaring + degree-8 Taylor on the pooled 15x15.
//
// 2 matrices per 32-thread block; 16 threads per matrix with 8x8 register
// tiles (FMA:LDS-phase ratio 16:1 per k-step). A-operand loads use symmetry
// of Y (A[r][k] = Y[k][r]) so both operands stream as float4.

#define NMM 32
#define LDM 36       // padded row stride (floats), float4-aligned
#define NP  15
#define LDP 16
#define DEG 15       // Chebyshev degree
#define TAYD 8       // exp Taylor degree
#define MPB 2        // matrices per block

__device__ __forceinline__ void gemm8x8(const float* __restrict__ Ys,
                                        const float* __restrict__ Bp,
                                        int r0, int c0, float t[8][8])
{
    #pragma unroll 8
    for (int kk = 0; kk < NMM; kk++) {
        const float* yr = Ys + kk * LDM;
        const float* br = Bp + kk * LDM;
        float4 a0 = *(const float4*)(yr + r0);
        float4 a1 = *(const float4*)(yr + r0 + 4);
        float4 b0 = *(const float4*)(br + c0);
        float4 b1 = *(const float4*)(br + c0 + 4);
        float aa[8] = {a0.x, a0.y, a0.z, a0.w, a1.x, a1.y, a1.z, a1.w};
        float bb[8] = {b0.x, b0.y, b0.z, b0.w, b1.x, b1.y, b1.z, b1.w};
        #pragma unroll
        for (int r = 0; r < 8; r++)
            #pragma unroll
            for (int c = 0; c < 8; c++)
                t[r][c] = fmaf(aa[r], bb[c], t[r][c]);
    }
}

__global__ __launch_bounds__(32)
void spd_log_pool_exp(const float* __restrict__ xin, float* __restrict__ yout)
{
    __shared__ __align__(16) float Ysh[MPB][NMM * LDM];
    __shared__ __align__(16) float Bua[MPB][NMM * LDM];
    __shared__ __align__(16) float Bub[MPB][NMM * LDM];
    __shared__ float norms[MPB][16];
    __shared__ float snrm[MPB];
    __shared__ float smax;

    const int tid = threadIdx.x;
    const int ml  = tid >> 4;        // matrix slot in block
    const int t16 = tid & 15;        // thread within matrix
    const size_t mat = (size_t)blockIdx.x * MPB + ml;

    float* Ys = Ysh[ml];
    float* Ap = Bua[ml];             // holds b_{k+2}; overwritten with b_k
    float* Bp = Bub[ml];             // holds b_{k+1}

    // Chebyshev constants for log on [0.98, 8.0]
    const float mC   = 4.49f;
    const float invh = 1.0f / 3.51f;
    const float zz   = 0.48148236f;
    const float invz = 1.0f / 0.48148236f;
    const float c0c  = 1.2933564f;   // log(m) - log(1+z^2)

    // z^DEG and top two coefficients
    float zp = 1.0f;
    #pragma unroll
    for (int q = 0; q < DEG; q++) zp *= zz;      // z^15
    const float cn   =  2.0f * zp / (float)DEG;              // k=15 (odd -> +)
    float zcur = zp * invz;                                   // z^14
    const float cnm1 = -2.0f * zcur / (float)(DEG - 1);       // k=14 (even -> -)

    // ---- load X; Y = (X - mI)/h ; Bp = c14 I + 2 c15 Y ; Ap = c15 I ----
    {
        const float4* Xv = (const float4*)(xin + mat * (NMM * NMM));
        const float tc = 2.0f * cn;
        #pragma unroll
        for (int q = 0; q < 16; q++) {
            int f  = t16 + 16 * q;          // float4 index 0..255
            int i  = f >> 3;
            int jb = (f & 7) << 2;
            float4 v = Xv[f];
            float4 dv, yv, bv, av;
            dv.x = (i == jb + 0) ? 1.f : 0.f;
            dv.y = (i == jb + 1) ? 1.f : 0.f;
            dv.z = (i == jb + 2) ? 1.f : 0.f;
            dv.w = (i == jb + 3) ? 1.f : 0.f;
            yv.x = (v.x - mC * dv.x) * invh;
            yv.y = (v.y - mC * dv.y) * invh;
            yv.z = (v.z - mC * dv.z) * invh;
            yv.w = (v.w - mC * dv.w) * invh;
            bv.x = fmaf(tc, yv.x, cnm1 * dv.x);
            bv.y = fmaf(tc, yv.y, cnm1 * dv.y);
            bv.z = fmaf(tc, yv.z, cnm1 * dv.z);
            bv.w = fmaf(tc, yv.w, cnm1 * dv.w);
            av.x = cn * dv.x; av.y = cn * dv.y; av.z = cn * dv.z; av.w = cn * dv.w;
            *(float4*)(Ys + i * LDM + jb) = yv;
            *(float4*)(Bp + i * LDM + jb) = bv;
            *(float4*)(Ap + i * LDM + jb) = av;
        }
    }

    // 8x8 tile: rows r0..r0+7, cols cT..cT+7
    const int r0 = (t16 >> 2) << 3;
    const int cT = (t16 & 3) << 3;

    // ---- Clenshaw downward: k = DEG-2 .. 1 ----
    #pragma unroll 1
    for (int k = DEG - 2; k >= 1; k--) {
        zcur *= invz;                                 // z^k
        float ck = 2.0f * zcur / (float)k;
        if ((k & 1) == 0) ck = -ck;

        __syncwarp();

        float t[8][8] = {};
        gemm8x8(Ys, Bp, r0, cT, t);

        // b_k = ck I + 2 t - b_{k+2}(own tile, in Ap)
        #pragma unroll
        for (int r = 0; r < 8; r++) {
            int gr = r0 + r;
            float* rowp = Ap + gr * LDM + cT;
            float4 p0 = *(const float4*)(rowp);
            float4 p1 = *(const float4*)(rowp + 4);
            float v[8];
            v[0] = 2.0f * t[r][0] - p0.x;
            v[1] = 2.0f * t[r][1] - p0.y;
            v[2] = 2.0f * t[r][2] - p0.z;
            v[3] = 2.0f * t[r][3] - p0.w;
            v[4] = 2.0f * t[r][4] - p1.x;
            v[5] = 2.0f * t[r][5] - p1.y;
            v[6] = 2.0f * t[r][6] - p1.z;
            v[7] = 2.0f * t[r][7] - p1.w;
            int dc = gr - cT;
            if (dc >= 0 && dc < 8) v[dc] += ck;
            *(float4*)(rowp)     = make_float4(v[0], v[1], v[2], v[3]);
            *(float4*)(rowp + 4) = make_float4(v[4], v[5], v[6], v[7]);
        }
        float* tmp = Ap; Ap = Bp; Bp = tmp;
    }

    // ---- final: S = c0 I + Y*b1 - b2   (Bp = b1, Ap = b2) ----
    __syncwarp();
    {
        float t[8][8] = {};
        gemm8x8(Ys, Bp, r0, cT, t);
        #pragma unroll
        for (int r = 0; r < 8; r++) {
            int gr = r0 + r;
            float* rowp = Ap + gr * LDM + cT;
            float4 p0 = *(const float4*)(rowp);
            float4 p1 = *(const float4*)(rowp + 4);
            float v[8];
            v[0] = t[r][0] - p0.x;
            v[1] = t[r][1] - p0.y;
            v[2] = t[r][2] - p0.z;
            v[3] = t[r][3] - p0.w;
            v[4] = t[r][4] - p1.x;
            v[5] = t[r][5] - p1.y;
            v[6] = t[r][6] - p1.z;
            v[7] = t[r][7] - p1.w;
            int dc = gr - cT;
            if (dc >= 0 && dc < 8) v[dc] += c0c;
            *(float4*)(rowp)     = make_float4(v[0], v[1], v[2], v[3]);
            *(float4*)(rowp + 4) = make_float4(v[4], v[5], v[6], v[7]);
        }
    }
    __syncwarp();   // S (in Ap) visible; all reads of Ys done

    // ---- MaxPool2d(4, stride 2): 32x32 -> 15x15 into Ys region ----
    float* P = Ys;
    for (int p = t16; p < NP * NP; p += 16) {
        int pi = p / NP, pj = p - pi * NP;
        float mx = -1e30f;
        #pragma unroll
        for (int a = 0; a < 4; a++)
            #pragma unroll
            for (int b = 0; b < 4; b++)
                mx = fmaxf(mx, Ap[(2 * pi + a) * LDM + (2 * pj + b)]);
        P[pi * LDP + pj] = mx;
    }
    __syncwarp();

    // ---- ||P||_inf, uniform scaling exponent across the block ----
    if (t16 < NP) {
        float acc = 0.f;
        #pragma unroll
        for (int j = 0; j < NP; j++) acc += fabsf(P[t16 * LDP + j]);
        norms[ml][t16] = acc;
    }
    __syncwarp();
    if (t16 == 0) {
        float m = 0.f;
        #pragma unroll
        for (int i = 0; i < NP; i++) m = fmaxf(m, norms[ml][i]);
        snrm[ml] = m;
    }
    __syncwarp();
    if (tid == 0) smax = fmaxf(snrm[0], snrm[1]);
    __syncwarp();

    int sexp = 0;
    {
        float t = smax;
        while (t > 0.25f && sexp < 40) { t *= 0.5f; sexp++; }
    }
    const float sc = ldexpf(1.0f, -sexp);
    for (int p = t16; p < NP * NP; p += 16) {
        int pi = p / NP, pj = p - pi * NP;
        P[pi * LDP + pj] *= sc;
    }
    __syncwarp();

    // ---- exp(M) via Horner Taylor; Ec = Bp region (b1 dead), Eo = Ap ----
    float* Ec = Bp;
    float* Eo = Ap;
    for (int p = t16; p < NP * NP; p += 16) {
        int pi = p / NP, pj = p - pi * NP;
        Ec[pi * LDP + pj] = (pi == pj) ? 1.0f : 0.0f;
    }
    __syncwarp();

    for (int d = TAYD; d >= 1; d--) {
        float invd = 1.0f / (float)d;
        for (int p = t16; p < NP * NP; p += 16) {
            int pi = p / NP, pj = p - pi * NP;
            float acc = 0.f;
            #pragma unroll
            for (int kq = 0; kq < NP; kq++)
                acc = fmaf(P[pi * LDP + kq], Ec[kq * LDP + pj], acc);
            Eo[pi * LDP + pj] = fmaf(acc, invd, (pi == pj) ? 1.0f : 0.0f);
        }
        __syncwarp();
        float* tmp = Ec; Ec = Eo; Eo = tmp;
    }

    // ---- repeated squaring (uniform count across block) ----
    for (int q = 0; q < sexp; q++) {
        for (int p = t16; p < NP * NP; p += 16) {
            int pi = p / NP, pj = p - pi * NP;
            float acc = 0.f;
            #pragma unroll
            for (int kq = 0; kq < NP; kq++)
                acc = fmaf(Ec[pi * LDP + kq], Ec[kq * LDP + pj], acc);
            Eo[pi * LDP + pj] = acc;
        }
        __syncwarp();
        float* tmp = Ec; Ec = Eo; Eo = tmp;
    }

    // ---- output [15x15] ----
    for (int p = t16; p < NP * NP; p += 16)
        yout[mat * (NP * NP) + p] = Ec[(p / NP) * LDP + (p % NP)];
}

extern "C" void kernel_launch(void* const* d_in, const int* in_sizes, int n_in,
                              void* d_out, int out_size)
{
    const float* x = (const float*)d_in[0];
    float* out = (float*)d_out;
    const int nmat = in_sizes[0] / (NMM * NMM);     // 32768
    spd_log_pool_exp<<<nmat / MPB, 32>>>(x, out);
}

// round 4
// speedup vs baseline: 1.0019x; 1.0019x over previous
#include <cuda_runtime.h>
#include <math.h>

// Fused LogEig -> MaxPool(4,2) -> ExpEig for batched 32x32 SPD matrices.
//
// LogEig: degree-15 Chebyshev expansion of log on [0.98, 8.0], evaluated with
// the Clenshaw recurrence  b_k = c_k I + 2 Y b_{k+1} - b_{k+2},
// f = c0 I + Y b_1 - b_2.  (lambda(x) in [1, ~5.8] provably, huge margin.)
// ExpEig: scaling-and-squaring + degree-8 Taylor on the pooled 15x15.
//
// 2 matrices per 32-thread block; 16 threads per matrix with 8x8 register
// tiles (FMA:LDS-phase ratio 16:1 per k-step). A-operand loads use symmetry
// of Y (A[r][k] = Y[k][r]) so both operands stream as float4.

#define NMM 32
#define LDM 36       // padded row stride (floats), float4-aligned
#define NP  15
#define LDP 16
#define DEG 15       // Chebyshev degree
#define TAYD 8       // exp Taylor degree
#define MPB 2        // matrices per block

__device__ __forceinline__ void gemm8x8(const float* __restrict__ Ys,
                                        const float* __restrict__ Bp,
                                        int r0, int c0, float t[8][8])
{
    #pragma unroll 8
    for (int kk = 0; kk < NMM; kk++) {
        const float* yr = Ys + kk * LDM;
        const float* br = Bp + kk * LDM;
        float4 a0 = *(const float4*)(yr + r0);
        float4 a1 = *(const float4*)(yr + r0 + 4);
        float4 b0 = *(const float4*)(br + c0);
        float4 b1 = *(const float4*)(br + c0 + 4);
        float aa[8] = {a0.x, a0.y, a0.z, a0.w, a1.x, a1.y, a1.z, a1.w};
        float bb[8] = {b0.x, b0.y, b0.z, b0.w, b1.x, b1.y, b1.z, b1.w};
        #pragma unroll
        for (int r = 0; r < 8; r++)
            #pragma unroll
            for (int c = 0; c < 8; c++)
                t[r][c] = fmaf(aa[r], bb[c], t[r][c]);
    }
}

__global__ __launch_bounds__(32)
void spd_log_pool_exp(const float* __restrict__ xin, float* __restrict__ yout)
{
    __shared__ __align__(16) float Ysh[MPB][NMM * LDM];
    __shared__ __align__(16) float Bua[MPB][NMM * LDM];
    __shared__ __align__(16) float Bub[MPB][NMM * LDM];
    __shared__ float norms[MPB][16];
    __shared__ float snrm[MPB];
    __shared__ float smax;

    const int tid = threadIdx.x;
    const int ml  = tid >> 4;        // matrix slot in block
    const int t16 = tid & 15;        // thread within matrix
    const size_t mat = (size_t)blockIdx.x * MPB + ml;

    float* Ys = Ysh[ml];
    float* Ap = Bua[ml];             // holds b_{k+2}; overwritten with b_k
    float* Bp = Bub[ml];             // holds b_{k+1}

    // Chebyshev constants for log on [0.98, 8.0]
    const float mC   = 4.49f;
    const float invh = 1.0f / 3.51f;
    const float zz   = 0.48148236f;
    const float invz = 1.0f / 0.48148236f;
    const float c0c  = 1.2933564f;   // log(m) - log(1+z^2)

    // z^DEG and top two coefficients
    float zp = 1.0f;
    #pragma unroll
    for (int q = 0; q < DEG; q++) zp *= zz;      // z^15
    const float cn   =  2.0f * zp / (float)DEG;              // k=15 (odd -> +)
    float zcur = zp * invz;                                   // z^14
    const float cnm1 = -2.0f * zcur / (float)(DEG - 1);       // k=14 (even -> -)

    // ---- load X; Y = (X - mI)/h ; Bp = c14 I + 2 c15 Y ; Ap = c15 I ----
    {
        const float4* Xv = (const float4*)(xin + mat * (NMM * NMM));
        const float tc = 2.0f * cn;
        #pragma unroll
        for (int q = 0; q < 16; q++) {
            int f  = t16 + 16 * q;          // float4 index 0..255
            int i  = f >> 3;
            int jb = (f & 7) << 2;
            float4 v = Xv[f];
            float4 dv, yv, bv, av;
            dv.x = (i == jb + 0) ? 1.f : 0.f;
            dv.y = (i == jb + 1) ? 1.f : 0.f;
            dv.z = (i == jb + 2) ? 1.f : 0.f;
            dv.w = (i == jb + 3) ? 1.f : 0.f;
            yv.x = (v.x - mC * dv.x) * invh;
            yv.y = (v.y - mC * dv.y) * invh;
            yv.z = (v.z - mC * dv.z) * invh;
            yv.w = (v.w - mC * dv.w) * invh;
            bv.x = fmaf(tc, yv.x, cnm1 * dv.x);
            bv.y = fmaf(tc, yv.y, cnm1 * dv.y);
            bv.z = fmaf(tc, yv.z, cnm1 * dv.z);
            bv.w = fmaf(tc, yv.w, cnm1 * dv.w);
            av.x = cn * dv.x; av.y = cn * dv.y; av.z = cn * dv.z; av.w = cn * dv.w;
            *(float4*)(Ys + i * LDM + jb) = yv;
            *(float4*)(Bp + i * LDM + jb) = bv;
            *(float4*)(Ap + i * LDM + jb) = av;
        }
    }

    // 8x8 tile: rows r0..r0+7, cols cT..cT+7
    const int r0 = (t16 >> 2) << 3;
    const int cT = (t16 & 3) << 3;

    // ---- Clenshaw downward: k = DEG-2 .. 1 ----
    #pragma unroll 1
    for (int k = DEG - 2; k >= 1; k--) {
        zcur *= invz;                                 // z^k
        float ck = 2.0f * zcur / (float)k;
        if ((k & 1) == 0) ck = -ck;

        __syncwarp();

        float t[8][8] = {};
        gemm8x8(Ys, Bp, r0, cT, t);

        // b_k = ck I + 2 t - b_{k+2}(own tile, in Ap)
        #pragma unroll
        for (int r = 0; r < 8; r++) {
            int gr = r0 + r;
            float* rowp = Ap + gr * LDM + cT;
            float4 p0 = *(const float4*)(rowp);
            float4 p1 = *(const float4*)(rowp + 4);
            float v[8];
            v[0] = 2.0f * t[r][0] - p0.x;
            v[1] = 2.0f * t[r][1] - p0.y;
            v[2] = 2.0f * t[r][2] - p0.z;
            v[3] = 2.0f * t[r][3] - p0.w;
            v[4] = 2.0f * t[r][4] - p1.x;
            v[5] = 2.0f * t[r][5] - p1.y;
            v[6] = 2.0f * t[r][6] - p1.z;
            v[7] = 2.0f * t[r][7] - p1.w;
            int dc = gr - cT;
            if (dc >= 0 && dc < 8) v[dc] += ck;
            *(float4*)(rowp)     = make_float4(v[0], v[1], v[2], v[3]);
            *(float4*)(rowp + 4) = make_float4(v[4], v[5], v[6], v[7]);
        }
        float* tmp = Ap; Ap = Bp; Bp = tmp;
    }

    // ---- final: S = c0 I + Y*b1 - b2   (Bp = b1, Ap = b2) ----
    __syncwarp();
    {
        float t[8][8] = {};
        gemm8x8(Ys, Bp, r0, cT, t);
        #pragma unroll
        for (int r = 0; r < 8; r++) {
            int gr = r0 + r;
            float* rowp = Ap + gr * LDM + cT;
            float4 p0 = *(const float4*)(rowp);
            float4 p1 = *(const float4*)(rowp + 4);
            float v[8];
            v[0] = t[r][0] - p0.x;
            v[1] = t[r][1] - p0.y;
            v[2] = t[r][2] - p0.z;
            v[3] = t[r][3] - p0.w;
            v[4] = t[r][4] - p1.x;
            v[5] = t[r][5] - p1.y;
            v[6] = t[r][6] - p1.z;
            v[7] = t[r][7] - p1.w;
            int dc = gr - cT;
            if (dc >= 0 && dc < 8) v[dc] += c0c;
            *(float4*)(rowp)     = make_float4(v[0], v[1], v[2], v[3]);
            *(float4*)(rowp + 4) = make_float4(v[4], v[5], v[6], v[7]);
        }
    }
    __syncwarp();   // S (in Ap) visible; all reads of Ys done

    // ---- MaxPool2d(4, stride 2): 32x32 -> 15x15 into Ys region ----
    float* P = Ys;
    for (int p = t16; p < NP * NP; p += 16) {
        int pi = p / NP, pj = p - pi * NP;
        float mx = -1e30f;
        #pragma unroll
        for (int a = 0; a < 4; a++)
            #pragma unroll
            for (int b = 0; b < 4; b++)
                mx = fmaxf(mx, Ap[(2 * pi + a) * LDM + (2 * pj + b)]);
        P[pi * LDP + pj] = mx;
    }
    __syncwarp();

    // ---- ||P||_inf, uniform scaling exponent across the block ----
    if (t16 < NP) {
        float acc = 0.f;
        #pragma unroll
        for (int j = 0; j < NP; j++) acc += fabsf(P[t16 * LDP + j]);
        norms[ml][t16] = acc;
    }
    __syncwarp();
    if (t16 == 0) {
        float m = 0.f;
        #pragma unroll
        for (int i = 0; i < NP; i++) m = fmaxf(m, norms[ml][i]);
        snrm[ml] = m;
    }
    __syncwarp();
    if (tid == 0) smax = fmaxf(snrm[0], snrm[1]);
    __syncwarp();

    int sexp = 0;
    {
        float t = smax;
        while (t > 0.25f && sexp < 40) { t *= 0.5f; sexp++; }
    }
    const float sc = ldexpf(1.0f, -sexp);
    for (int p = t16; p < NP * NP; p += 16) {
        int pi = p / NP, pj = p - pi * NP;
        P[pi * LDP + pj] *= sc;
    }
    __syncwarp();

    // ---- exp(M) via Horner Taylor; Ec = Bp region (b1 dead), Eo = Ap ----
    float* Ec = Bp;
    float* Eo = Ap;
    for (int p = t16; p < NP * NP; p += 16) {
        int pi = p / NP, pj = p - pi * NP;
        Ec[pi * LDP + pj] = (pi == pj) ? 1.0f : 0.0f;
    }
    __syncwarp();

    for (int d = TAYD; d >= 1; d--) {
        float invd = 1.0f / (float)d;
        for (int p = t16; p < NP * NP; p += 16) {
            int pi = p / NP, pj = p - pi * NP;
            float acc = 0.f;
            #pragma unroll
            for (int kq = 0; kq < NP; kq++)
                acc = fmaf(P[pi * LDP + kq], Ec[kq * LDP + pj], acc);
            Eo[pi * LDP + pj] = fmaf(acc, invd, (pi == pj) ? 1.0f : 0.0f);
        }
        __syncwarp();
        float* tmp = Ec; Ec = Eo; Eo = tmp;
    }

    // ---- repeated squaring (uniform count across block) ----
    for (int q = 0; q < sexp; q++) {
        for (int p = t16; p < NP * NP; p += 16) {
            int pi = p / NP, pj = p - pi * NP;
            float acc = 0.f;
            #pragma unroll
            for (int kq = 0; kq < NP; kq++)
                acc = fmaf(Ec[pi * LDP + kq], Ec[kq * LDP + pj], acc);
            Eo[pi * LDP + pj] = acc;
        }
        __syncwarp();
        float* tmp = Ec; Ec = Eo; Eo = tmp;
    }

    // ---- output [15x15] ----
    for (int p = t16; p < NP * NP; p += 16)
        yout[mat * (NP * NP) + p] = Ec[(p / NP) * LDP + (p % NP)];
}

extern "C" void kernel_launch(void* const* d_in, const int* in_sizes, int n_in,
                              void* d_out, int out_size)
{
    const float* x = (const float*)d_in[0];
    float* out = (float*)d_out;
    const int nmat = in_sizes[0] / (NMM * NMM);     // 32768
    spd_log_pool_exp<<<nmat / MPB, 32>>>(x, out);
}

// round 6
// speedup vs baseline: 1.4889x; 1.4861x over previous
#include <cuda_runtime.h>
#include <math.h>

// Fused LogEig -> MaxPool(4,2) -> ExpEig for batched 32x32 SPD matrices.
//
// LogEig: degree-15 Chebyshev approximant of log on [0.98, 8.0], converted on
// the HOST to monomial coefficients (passed by value as kernel args) and
// evaluated Paterson-Stockmeyer style in Y^2:
//   P(Y) = B0 + Y2(B1 + Y2(... + Y2*B7)),  B_a = a_{2a} I + a_{2a+1} Y.
// => 8 GEMMs total.
// ExpEig: trace-shift + scaling-and-squaring + degree-6 Taylor on pooled 15x15.
//
// 2 matrices per 32-thread block, 16 threads / matrix, 8x8 register tiles.
// Per-matrix smem buffers are staggered by +4 floats so the two half-warps
// hit disjoint shared-memory bank sets on GEMM loads.

#define NMM 32
#define LDM 36
#define MATSZ (NMM * LDM + 4)   // +16B stagger
#define NP  15
#define LDP 16
#define MPB 2
#define TAYD 6

struct Coefs { float a[16]; };

// ---------- 8x8-tile GEMM: t += A * B (A symmetric: rows read as columns) ----------
__device__ __forceinline__ void gemm8x8(const float* __restrict__ A,
                                        const float* __restrict__ B,
                                        int r0, int c0, float t[8][8])
{
    #pragma unroll 8
    for (int kk = 0; kk < NMM; kk++) {
        const float* ar = A + kk * LDM;
        const float* br = B + kk * LDM;
        float4 a0 = *(const float4*)(ar + r0);
        float4 a1 = *(const float4*)(ar + r0 + 4);
        float4 b0 = *(const float4*)(br + c0);
        float4 b1 = *(const float4*)(br + c0 + 4);
        float aa[8] = {a0.x, a0.y, a0.z, a0.w, a1.x, a1.y, a1.z, a1.w};
        float bb[8] = {b0.x, b0.y, b0.z, b0.w, b1.x, b1.y, b1.z, b1.w};
        #pragma unroll
        for (int r = 0; r < 8; r++)
            #pragma unroll
            for (int c = 0; c < 8; c++)
                t[r][c] = fmaf(aa[r], bb[c], t[r][c]);
    }
}

__global__ __launch_bounds__(32)
void spd_log_pool_exp(const float* __restrict__ xin, float* __restrict__ yout,
                      const Coefs CF)
{
    __shared__ __align__(16) float Ysh [MPB * MATSZ];   // Y; later pooled P
    __shared__ __align__(16) float Y2sh[MPB * MATSZ];   // Y^2; later exp ping
    __shared__ __align__(16) float Acsh[MPB * MATSZ];   // Horner acc; later exp pong
    __shared__ float norms[MPB][16];
    __shared__ float snrm[MPB];
    __shared__ float smu[MPB];

    const int tid = threadIdx.x;
    const int ml  = tid >> 4;
    const int t16 = tid & 15;
    const size_t mat = (size_t)blockIdx.x * MPB + ml;

    float* Ys  = Ysh  + ml * MATSZ;
    float* Y2s = Y2sh + ml * MATSZ;
    float* Acc = Acsh + ml * MATSZ;

    const float mC   = 4.49f;
    const float invh = 1.0f / 3.51f;
    const float a14  = CF.a[14];
    const float a15  = CF.a[15];

    // ---- load X; Y = (X - mI)/h ; Acc = a14 I + a15 Y ----
    {
        const float4* Xv = (const float4*)(xin + mat * (NMM * NMM));
        #pragma unroll
        for (int q = 0; q < 16; q++) {
            int f  = t16 + 16 * q;
            int i  = f >> 3;
            int jb = (f & 7) << 2;
            float4 v = Xv[f];
            float4 dv, yv, av;
            dv.x = (i == jb + 0) ? 1.f : 0.f;
            dv.y = (i == jb + 1) ? 1.f : 0.f;
            dv.z = (i == jb + 2) ? 1.f : 0.f;
            dv.w = (i == jb + 3) ? 1.f : 0.f;
            yv.x = (v.x - mC * dv.x) * invh;
            yv.y = (v.y - mC * dv.y) * invh;
            yv.z = (v.z - mC * dv.z) * invh;
            yv.w = (v.w - mC * dv.w) * invh;
            av.x = fmaf(a15, yv.x, a14 * dv.x);
            av.y = fmaf(a15, yv.y, a14 * dv.y);
            av.z = fmaf(a15, yv.z, a14 * dv.z);
            av.w = fmaf(a15, yv.w, a14 * dv.w);
            *(float4*)(Ys  + i * LDM + jb) = yv;
            *(float4*)(Acc + i * LDM + jb) = av;
        }
    }

    const int r0 = (t16 >> 2) << 3;
    const int cT = (t16 & 3) << 3;

    __syncwarp();

    // ---- GEMM 1: Y2 = Y * Y ----
    {
        float t[8][8] = {};
        gemm8x8(Ys, Ys, r0, cT, t);
        #pragma unroll
        for (int r = 0; r < 8; r++) {
            *(float4*)(Y2s + (r0 + r) * LDM + cT)     = make_float4(t[r][0], t[r][1], t[r][2], t[r][3]);
            *(float4*)(Y2s + (r0 + r) * LDM + cT + 4) = make_float4(t[r][4], t[r][5], t[r][6], t[r][7]);
        }
    }
    __syncwarp();

    // ---- Horner in Y2: Acc = Acc*Y2 + (a_{2a} I + a_{2a+1} Y), a = 6..0 ----
    #pragma unroll 1
    for (int a = 6; a >= 0; a--) {
        const float k0 = CF.a[2 * a];
        const float k1 = CF.a[2 * a + 1];

        float t[8][8] = {};
        gemm8x8(Acc, Y2s, r0, cT, t);
        __syncwarp();   // all reads of Acc complete before overwrite

        #pragma unroll
        for (int r = 0; r < 8; r++) {
            int gr = r0 + r;
            float4 y0 = *(const float4*)(Ys + gr * LDM + cT);
            float4 y1 = *(const float4*)(Ys + gr * LDM + cT + 4);
            float v[8];
            v[0] = fmaf(k1, y0.x, t[r][0]);
            v[1] = fmaf(k1, y0.y, t[r][1]);
            v[2] = fmaf(k1, y0.z, t[r][2]);
            v[3] = fmaf(k1, y0.w, t[r][3]);
            v[4] = fmaf(k1, y1.x, t[r][4]);
            v[5] = fmaf(k1, y1.y, t[r][5]);
            v[6] = fmaf(k1, y1.z, t[r][6]);
            v[7] = fmaf(k1, y1.w, t[r][7]);
            int dc = gr - cT;
            if (dc >= 0 && dc < 8) v[dc] += k0;
            *(float4*)(Acc + gr * LDM + cT)     = make_float4(v[0], v[1], v[2], v[3]);
            *(float4*)(Acc + gr * LDM + cT + 4) = make_float4(v[4], v[5], v[6], v[7]);
        }
        __syncwarp();   // new Acc visible before next GEMM
    }
    // Acc = log(X)

    // ---- MaxPool2d(4, stride 2): 32x32 -> 15x15 into Ys region ----
    float* P = Ys;
    for (int p = t16; p < NP * NP; p += 16) {
        int pi = p / NP, pj = p - pi * NP;
        float mx = -1e30f;
        #pragma unroll
        for (int a = 0; a < 4; a++)
            #pragma unroll
            for (int b = 0; b < 4; b++)
                mx = fmaxf(mx, Acc[(2 * pi + a) * LDM + (2 * pj + b)]);
        P[pi * LDP + pj] = mx;
    }
    __syncwarp();

    // ---- trace shift: mu = tr(P)/15 ----
    if (t16 == 0) {
        float s = 0.f;
        #pragma unroll
        for (int i = 0; i < NP; i++) s += P[i * LDP + i];
        smu[ml] = s * (1.0f / (float)NP);
    }
    __syncwarp();
    const float mu = smu[ml];
    for (int p = t16; p < NP * NP; p += 16) {
        int pi = p / NP, pj = p - pi * NP;
        if (pi == pj) P[pi * LDP + pj] -= mu;
    }
    __syncwarp();

    // ---- ||P - mu I||_inf ----
    if (t16 < NP) {
        float acc = 0.f;
        #pragma unroll
        for (int j = 0; j < NP; j++) acc += fabsf(P[t16 * LDP + j]);
        norms[ml][t16] = acc;
    }
    __syncwarp();
    if (t16 == 0) {
        float m = 0.f;
        #pragma unroll
        for (int i = 0; i < NP; i++) m = fmaxf(m, norms[ml][i]);
        snrm[ml] = m;
    }
    __syncwarp();
    const float smax = fmaxf(snrm[0], snrm[1]);   // uniform over the warp

    int sexp = 0;
    {
        float t = smax;
        while (t > 0.25f && sexp < 40) { t *= 0.5f; sexp++; }
    }
    const float sc = ldexpf(1.0f, -sexp);
    for (int p = t16; p < NP * NP; p += 16) {
        int pi = p / NP, pj = p - pi * NP;
        P[pi * LDP + pj] *= sc;
    }
    __syncwarp();

    // ---- exp(M) via degree-6 Taylor Horner ----
    float* Ec = Y2s;
    float* Eo = Acc;
    for (int p = t16; p < NP * NP; p += 16) {
        int pi = p / NP, pj = p - pi * NP;
        Ec[pi * LDP + pj] = (pi == pj) ? 1.0f : 0.0f;
    }
    __syncwarp();

    #pragma unroll 1
    for (int d = TAYD; d >= 1; d--) {
        const float invd = 1.0f / (float)d;
        for (int p = t16; p < NP * NP; p += 16) {
            int pi = p / NP, pj = p - pi * NP;
            float acc = 0.f;
            #pragma unroll
            for (int kq = 0; kq < NP; kq++)
                acc = fmaf(P[pi * LDP + kq], Ec[kq * LDP + pj], acc);
            Eo[pi * LDP + pj] = fmaf(acc, invd, (pi == pj) ? 1.0f : 0.0f);
        }
        __syncwarp();
        float* tmp = Ec; Ec = Eo; Eo = tmp;
    }

    // ---- repeated squaring (uniform count across the warp) ----
    for (int q = 0; q < sexp; q++) {
        for (int p = t16; p < NP * NP; p += 16) {
            int pi = p / NP, pj = p - pi * NP;
            float acc = 0.f;
            #pragma unroll
            for (int kq = 0; kq < NP; kq++)
                acc = fmaf(Ec[pi * LDP + kq], Ec[kq * LDP + pj], acc);
            Eo[pi * LDP + pj] = acc;
        }
        __syncwarp();
        float* tmp = Ec; Ec = Eo; Eo = tmp;
    }

    // ---- output: e^mu * E ----
    const float emu = expf(mu);
    for (int p = t16; p < NP * NP; p += 16)
        yout[mat * (NP * NP) + p] = emu * Ec[(p / NP) * LDP + (p % NP)];
}

extern "C" void kernel_launch(void* const* d_in, const int* in_sizes, int n_in,
                              void* d_out, int out_size)
{
    const float* x = (const float*)d_in[0];
    float* out = (float*)d_out;
    const int nmat = in_sizes[0] / (NMM * NMM);   // 32768

    // ---- host: Chebyshev coefficients of log on [0.98, 8.0] -> monomial in Y ----
    const double m = 4.49, h = 3.51;
    const double r = h / m;
    const double z = (1.0 - sqrt(1.0 - r * r)) / r;
    double c[16];
    c[0] = log(m) - log(1.0 + z * z);
    {
        double zp = 1.0;
        for (int k = 1; k < 16; k++) { zp *= z; c[k] = ((k & 1) ? 2.0 : -2.0) * zp / (double)k; }
    }
    double Tm2[16] = {0}, Tm1[16] = {0}, acc[16] = {0};
    Tm2[0] = 1.0; Tm1[1] = 1.0;
    acc[0] += c[0]; acc[1] += c[1];
    for (int k = 2; k < 16; k++) {
        double Tk[16] = {0};
        for (int j = 0; j < 15; j++) Tk[j + 1] += 2.0 * Tm1[j];
        for (int j = 0; j < 16; j++) Tk[j] -= Tm2[j];
        for (int j = 0; j < 16; j++) acc[j] += c[k] * Tk[j];
        for (int j = 0; j < 16; j++) { Tm2[j] = Tm1[j]; Tm1[j] = Tk[j]; }
    }
    Coefs cf;
    for (int j = 0; j < 16; j++) cf.a[j] = (float)acc[j];

    spd_log_pool_exp<<<nmat / MPB, 32>>>(x, out, cf);
}

// round 7
// speedup vs baseline: 2.7491x; 1.8464x over previous
#include <cuda_runtime.h>
#include <math.h>

// Fused LogEig -> MaxPool(4,2) -> ExpEig for batched 32x32 SPD matrices.
//
// LogEig: degree-11 Chebyshev approximant of log on [1.0, 7.0], converted on
// the host to monomial coefficients and evaluated Paterson-Stockmeyer style
// in Y^2: P(Y) = B0 + W(B1 + W(...(B5))), W = Y^2, B_a = a_{2a} I + a_{2a+1} Y.
// => 6 GEMMs total.
// ExpEig: trace-shift + scaling-and-squaring + degree-6 Taylor, evaluated
// ROW-PARALLEL (thread i owns row i; P-row cached in registers; Ec rows read
// as warp-broadcast LDS.128).
//
// 2 matrices per 32-thread block, 16 threads / matrix, 8x8 register tiles.

#define NMM 32
#define LDM 36
#define MATSZ (NMM * LDM + 4)   // +16B stagger: half-warps on disjoint banks
#define NP  15
#define LDP 16
#define MPB 2
#define TAYD 6

struct Coefs { float a[12]; };

// t += A^T * B == A*B for symmetric A (row kk read as column)
__device__ __forceinline__ void gemm8x8(const float* __restrict__ A,
                                        const float* __restrict__ B,
                                        int r0, int c0, float t[8][8])
{
    #pragma unroll 8
    for (int kk = 0; kk < NMM; kk++) {
        const float* ar = A + kk * LDM;
        const float* br = B + kk * LDM;
        float4 a0 = *(const float4*)(ar + r0);
        float4 a1 = *(const float4*)(ar + r0 + 4);
        float4 b0 = *(const float4*)(br + c0);
        float4 b1 = *(const float4*)(br + c0 + 4);
        float aa[8] = {a0.x, a0.y, a0.z, a0.w, a1.x, a1.y, a1.z, a1.w};
        float bb[8] = {b0.x, b0.y, b0.z, b0.w, b1.x, b1.y, b1.z, b1.w};
        #pragma unroll
        for (int r = 0; r < 8; r++)
            #pragma unroll
            for (int c = 0; c < 8; c++)
                t[r][c] = fmaf(aa[r], bb[c], t[r][c]);
    }
}

__global__ __launch_bounds__(32)
void spd_log_pool_exp(const float* __restrict__ xin, float* __restrict__ yout,
                      const Coefs CF)
{
    __shared__ __align__(16) float Ysh [MPB * MATSZ];   // Y; later pooled P
    __shared__ __align__(16) float Y2sh[MPB * MATSZ];   // Y^2; later exp ping
    __shared__ __align__(16) float Acsh[MPB * MATSZ];   // Horner acc; later exp pong
    __shared__ float norms[MPB][16];
    __shared__ float snrm[MPB];
    __shared__ float smu[MPB];

    const int tid = threadIdx.x;
    const int ml  = tid >> 4;
    const int t16 = tid & 15;
    const size_t mat = (size_t)blockIdx.x * MPB + ml;

    float* Ys  = Ysh  + ml * MATSZ;
    float* Y2s = Y2sh + ml * MATSZ;
    float* Acc = Acsh + ml * MATSZ;

    const float mC   = 4.0f;            // interval [1.0, 7.0]
    const float invh = 1.0f / 3.0f;
    const float a10  = CF.a[10];
    const float a11  = CF.a[11];

    // ---- load X; Y = (X - mI)/h ; Acc = a10 I + a11 Y ----
    {
        const float4* Xv = (const float4*)(xin + mat * (NMM * NMM));
        #pragma unroll
        for (int q = 0; q < 16; q++) {
            int f  = t16 + 16 * q;
            int i  = f >> 3;
            int jb = (f & 7) << 2;
            float4 v = Xv[f];
            float4 dv, yv, av;
            dv.x = (i == jb + 0) ? 1.f : 0.f;
            dv.y = (i == jb + 1) ? 1.f : 0.f;
            dv.z = (i == jb + 2) ? 1.f : 0.f;
            dv.w = (i == jb + 3) ? 1.f : 0.f;
            yv.x = (v.x - mC * dv.x) * invh;
            yv.y = (v.y - mC * dv.y) * invh;
            yv.z = (v.z - mC * dv.z) * invh;
            yv.w = (v.w - mC * dv.w) * invh;
            av.x = fmaf(a11, yv.x, a10 * dv.x);
            av.y = fmaf(a11, yv.y, a10 * dv.y);
            av.z = fmaf(a11, yv.z, a10 * dv.z);
            av.w = fmaf(a11, yv.w, a10 * dv.w);
            *(float4*)(Ys  + i * LDM + jb) = yv;
            *(float4*)(Acc + i * LDM + jb) = av;
        }
    }

    const int r0 = (t16 >> 2) << 3;
    const int cT = (t16 & 3) << 3;

    __syncwarp();

    // ---- GEMM 1: W = Y * Y ----
    {
        float t[8][8] = {};
        gemm8x8(Ys, Ys, r0, cT, t);
        #pragma unroll
        for (int r = 0; r < 8; r++) {
            *(float4*)(Y2s + (r0 + r) * LDM + cT)     = make_float4(t[r][0], t[r][1], t[r][2], t[r][3]);
            *(float4*)(Y2s + (r0 + r) * LDM + cT + 4) = make_float4(t[r][4], t[r][5], t[r][6], t[r][7]);
        }
    }
    __syncwarp();

    // ---- Horner in W: Acc = Acc*W + (a_{2a} I + a_{2a+1} Y), a = 4..0 ----
    #pragma unroll 1
    for (int a = 4; a >= 0; a--) {
        const float k0 = CF.a[2 * a];
        const float k1 = CF.a[2 * a + 1];

        float t[8][8] = {};
        gemm8x8(Acc, Y2s, r0, cT, t);
        __syncwarp();   // all reads of Acc complete before overwrite

        #pragma unroll
        for (int r = 0; r < 8; r++) {
            int gr = r0 + r;
            float4 y0 = *(const float4*)(Ys + gr * LDM + cT);
            float4 y1 = *(const float4*)(Ys + gr * LDM + cT + 4);
            float v[8];
            v[0] = fmaf(k1, y0.x, t[r][0]);
            v[1] = fmaf(k1, y0.y, t[r][1]);
            v[2] = fmaf(k1, y0.z, t[r][2]);
            v[3] = fmaf(k1, y0.w, t[r][3]);
            v[4] = fmaf(k1, y1.x, t[r][4]);
            v[5] = fmaf(k1, y1.y, t[r][5]);
            v[6] = fmaf(k1, y1.z, t[r][6]);
            v[7] = fmaf(k1, y1.w, t[r][7]);
            int dc = gr - cT;
            if (dc >= 0 && dc < 8) v[dc] += k0;
            *(float4*)(Acc + gr * LDM + cT)     = make_float4(v[0], v[1], v[2], v[3]);
            *(float4*)(Acc + gr * LDM + cT + 4) = make_float4(v[4], v[5], v[6], v[7]);
        }
        __syncwarp();
    }
    // Acc = log(X)

    // ---- MaxPool2d(4, stride 2): 32x32 -> 15x15 into Ys region ----
    float* P = Ys;
    for (int p = t16; p < NP * NP; p += 16) {
        int pi = p / NP, pj = p - pi * NP;
        float mx = -1e30f;
        #pragma unroll
        for (int a = 0; a < 4; a++)
            #pragma unroll
            for (int b = 0; b < 4; b++)
                mx = fmaxf(mx, Acc[(2 * pi + a) * LDM + (2 * pj + b)]);
        P[pi * LDP + pj] = mx;
    }
    __syncwarp();

    // ---- trace shift: mu = tr(P)/15 ----
    if (t16 == 0) {
        float s = 0.f;
        #pragma unroll
        for (int i = 0; i < NP; i++) s += P[i * LDP + i];
        smu[ml] = s * (1.0f / (float)NP);
    }
    __syncwarp();
    const float mu = smu[ml];
    if (t16 < NP) P[t16 * LDP + t16] -= mu;
    __syncwarp();

    // ---- ||P - mu I||_inf ----
    if (t16 < NP) {
        float acc = 0.f;
        #pragma unroll
        for (int j = 0; j < NP; j++) acc += fabsf(P[t16 * LDP + j]);
        norms[ml][t16] = acc;
    }
    __syncwarp();
    if (t16 == 0) {
        float m = 0.f;
        #pragma unroll
        for (int i = 0; i < NP; i++) m = fmaxf(m, norms[ml][i]);
        snrm[ml] = m;
    }
    __syncwarp();
    const float smax = fmaxf(snrm[0], snrm[1]);   // warp-uniform

    int sexp = 0;
    {
        float t = smax;
        while (t > 0.25f && sexp < 40) { t *= 0.5f; sexp++; }
    }
    const float sc = ldexpf(1.0f, -sexp);

    // ---- row-parallel exp: thread i owns row i; P-row cached in regs ----
    // Ec/Eo staggered so the two half-warps broadcast from disjoint banks.
    float* EcA = Y2sh + ml * MATSZ + ml * 12;   // (MATSZ+12) % 32 == 16
    float* EoA = Acsh + ml * MATSZ + ml * 12;

    float prow[16];
    float erow[16];
    if (t16 < NP) {
        float4* pr = (float4*)prow;
        pr[0] = *(const float4*)(P + t16 * LDP);
        pr[1] = *(const float4*)(P + t16 * LDP + 4);
        pr[2] = *(const float4*)(P + t16 * LDP + 8);
        pr[3] = *(const float4*)(P + t16 * LDP + 12);
        #pragma unroll
        for (int j = 0; j < 16; j++) prow[j] *= sc;
        // E = I + M/TAYD   (first Horner step, M*I folded away)
        const float it0 = 1.0f / (float)TAYD;
        #pragma unroll
        for (int j = 0; j < 16; j++) erow[j] = prow[j] * it0 + ((j == t16) ? 1.0f : 0.0f);
        float4* er = (float4*)erow;
        *(float4*)(EcA + t16 * LDP)      = er[0];
        *(float4*)(EcA + t16 * LDP + 4)  = er[1];
        *(float4*)(EcA + t16 * LDP + 8)  = er[2];
        *(float4*)(EcA + t16 * LDP + 12) = er[3];
    }
    __syncwarp();

    // Taylor Horner: E <- I + (M*E)/d, d = TAYD-1 .. 1
    #pragma unroll 1
    for (int d = TAYD - 1; d >= 1; d--) {
        const float invd = 1.0f / (float)d;
        if (t16 < NP) {
            float acc[16];
            #pragma unroll
            for (int j = 0; j < 16; j++) acc[j] = 0.f;
            #pragma unroll
            for (int k = 0; k < NP; k++) {
                const float* ek = EcA + k * LDP;
                float4 e0 = *(const float4*)(ek);
                float4 e1 = *(const float4*)(ek + 4);
                float4 e2 = *(const float4*)(ek + 8);
                float4 e3 = *(const float4*)(ek + 12);
                float ev[16] = {e0.x, e0.y, e0.z, e0.w, e1.x, e1.y, e1.z, e1.w,
                                e2.x, e2.y, e2.z, e2.w, e3.x, e3.y, e3.z, e3.w};
                float pk = prow[k];
                #pragma unroll
                for (int j = 0; j < 15; j++) acc[j] = fmaf(pk, ev[j], acc[j]);
            }
            #pragma unroll
            for (int j = 0; j < 16; j++)
                erow[j] = fmaf(acc[j], invd, (j == t16) ? 1.0f : 0.0f);
            float4* er = (float4*)erow;
            *(float4*)(EoA + t16 * LDP)      = er[0];
            *(float4*)(EoA + t16 * LDP + 4)  = er[1];
            *(float4*)(EoA + t16 * LDP + 8)  = er[2];
            *(float4*)(EoA + t16 * LDP + 12) = er[3];
        }
        __syncwarp();
        float* tmp = EcA; EcA = EoA; EoA = tmp;
    }

    // repeated squaring: E <- E*E (own row stays in erow)
    #pragma unroll 1
    for (int q = 0; q < sexp; q++) {
        if (t16 < NP) {
            float acc[16];
            #pragma unroll
            for (int j = 0; j < 16; j++) acc[j] = 0.f;
            #pragma unroll
            for (int k = 0; k < NP; k++) {
                const float* ek = EcA + k * LDP;
                float4 e0 = *(const float4*)(ek);
                float4 e1 = *(const float4*)(ek + 4);
                float4 e2 = *(const float4*)(ek + 8);
                float4 e3 = *(const float4*)(ek + 12);
                float ev[16] = {e0.x, e0.y, e0.z, e0.w, e1.x, e1.y, e1.z, e1.w,
                                e2.x, e2.y, e2.z, e2.w, e3.x, e3.y, e3.z, e3.w};
                float ak = erow[k];
                #pragma unroll
                for (int j = 0; j < 15; j++) acc[j] = fmaf(ak, ev[j], acc[j]);
            }
            #pragma unroll
            for (int j = 0; j < 16; j++) erow[j] = acc[j];
            float4* er = (float4*)erow;
            *(float4*)(EoA + t16 * LDP)      = er[0];
            *(float4*)(EoA + t16 * LDP + 4)  = er[1];
            *(float4*)(EoA + t16 * LDP + 8)  = er[2];
            *(float4*)(EoA + t16 * LDP + 12) = er[3];
        }
        __syncwarp();
        float* tmp = EcA; EcA = EoA; EoA = tmp;
    }

    // ---- output: e^mu * E, straight from registers ----
    if (t16 < NP) {
        const float emu = expf(mu);
        float* orow = yout + mat * (NP * NP) + t16 * NP;
        #pragma unroll
        for (int j = 0; j < NP; j++) orow[j] = emu * erow[j];
    }
}

extern "C" void kernel_launch(void* const* d_in, const int* in_sizes, int n_in,
                              void* d_out, int out_size)
{
    const float* x = (const float*)d_in[0];
    float* out = (float*)d_out;
    const int nmat = in_sizes[0] / (NMM * NMM);   // 32768

    // ---- host: degree-11 Chebyshev coefs of log on [1.0, 7.0] -> monomial in Y ----
    const double m = 4.0, h = 3.0;
    const double r = h / m;
    const double z = (1.0 - sqrt(1.0 - r * r)) / r;
    double c[12];
    c[0] = log(m) - log(1.0 + z * z);
    {
        double zp = 1.0;
        for (int k = 1; k < 12; k++) { zp *= z; c[k] = ((k & 1) ? 2.0 : -2.0) * zp / (double)k; }
    }
    double Tm2[12] = {0}, Tm1[12] = {0}, acc[12] = {0};
    Tm2[0] = 1.0; Tm1[1] = 1.0;
    acc[0] += c[0]; acc[1] += c[1];
    for (int k = 2; k < 12; k++) {
        double Tk[12] = {0};
        for (int j = 0; j < 11; j++) Tk[j + 1] += 2.0 * Tm1[j];
        for (int j = 0; j < 12; j++) Tk[j] -= Tm2[j];
        for (int j = 0; j < 12; j++) acc[j] += c[k] * Tk[j];
        for (int j = 0; j < 12; j++) { Tm2[j] = Tm1[j]; Tm1[j] = Tk[j]; }
    }
    Coefs cf;
    for (int j = 0; j < 12; j++) cf.a[j] = (float)acc[j];

    spd_log_pool_exp<<<nmat / MPB, 32>>>(x, out, cf);
}

// round 8
// speedup vs baseline: 2.9175x; 1.0613x over previous
#include <cuda_runtime.h>
#include <math.h>

// Fused LogEig -> MaxPool(4,2) -> ExpEig for batched 32x32 SPD matrices.
//
// LogEig: degree-9 Chebyshev approximant of log on [1.0, 7.0], converted on
// the host to monomial coefficients, evaluated Paterson-Stockmeyer in W = Y^2:
//   P(Y) = B0 + W(B1 + W(B2 + W(B3 + W*B4))),  B_a = a_{2a} I + a_{2a+1} Y
// => 5 GEMMs total. Each thread caches its own 8x8 Y-tile in REGISTERS so the
// Y smem buffer can be reused in-place as the Horner accumulator => only TWO
// 32x36 smem buffers per matrix => 18.7KB/block => 12 blocks/SM (was 8).
// ExpEig: trace-shift + scaling-and-squaring + degree-6 Taylor, row-parallel.
//
// 2 matrices per 32-thread block, 16 threads / matrix, 8x8 register tiles.
// Per-matrix buffers staggered +4 floats: half-warps on disjoint bank sets.

#define NMM 32
#define LDM 36
#define MATSZ (NMM * LDM + 4)
#define NP  15
#define LDP 16
#define MPB 2
#define TAYD 6

struct Coefs { float a[10]; };

// t += A * B for symmetric A (row kk read as column kk)
__device__ __forceinline__ void gemm8x8(const float* __restrict__ A,
                                        const float* __restrict__ B,
                                        int r0, int c0, float t[8][8])
{
    #pragma unroll 8
    for (int kk = 0; kk < NMM; kk++) {
        const float* ar = A + kk * LDM;
        const float* br = B + kk * LDM;
        float4 a0 = *(const float4*)(ar + r0);
        float4 a1 = *(const float4*)(ar + r0 + 4);
        float4 b0 = *(const float4*)(br + c0);
        float4 b1 = *(const float4*)(br + c0 + 4);
        float aa[8] = {a0.x, a0.y, a0.z, a0.w, a1.x, a1.y, a1.z, a1.w};
        float bb[8] = {b0.x, b0.y, b0.z, b0.w, b1.x, b1.y, b1.z, b1.w};
        #pragma unroll
        for (int r = 0; r < 8; r++)
            #pragma unroll
            for (int c = 0; c < 8; c++)
                t[r][c] = fmaf(aa[r], bb[c], t[r][c]);
    }
}

__global__ __launch_bounds__(32)
void spd_log_pool_exp(const float* __restrict__ xin, float* __restrict__ yout,
                      const Coefs CF)
{
    __shared__ __align__(16) float B1sh[MPB * MATSZ];  // Y -> Acc -> log(X)
    __shared__ __align__(16) float B2sh[MPB * MATSZ];  // W  -> P / Ec / Eo
    __shared__ float norms[MPB][16];
    __shared__ float snrm[MPB];
    __shared__ float smu[MPB];

    const int tid = threadIdx.x;
    const int ml  = tid >> 4;
    const int t16 = tid & 15;
    const size_t mat = (size_t)blockIdx.x * MPB + ml;

    float* B1 = B1sh + ml * MATSZ;
    float* B2 = B2sh + ml * MATSZ;

    const float mC   = 4.0f;          // interval [1.0, 7.0]
    const float invh = 1.0f / 3.0f;

    // ---- load X; Y = (X - mI)/h into B1 ----
    {
        const float4* Xv = (const float4*)(xin + mat * (NMM * NMM));
        #pragma unroll
        for (int q = 0; q < 16; q++) {
            int f  = t16 + 16 * q;
            int i  = f >> 3;
            int jb = (f & 7) << 2;
            float4 v = Xv[f];
            float4 yv;
            yv.x = (v.x - ((i == jb + 0) ? mC : 0.f)) * invh;
            yv.y = (v.y - ((i == jb + 1) ? mC : 0.f)) * invh;
            yv.z = (v.z - ((i == jb + 2) ? mC : 0.f)) * invh;
            yv.w = (v.w - ((i == jb + 3) ? mC : 0.f)) * invh;
            *(float4*)(B1 + i * LDM + jb) = yv;
        }
    }

    const int r0 = (t16 >> 2) << 3;
    const int cT = (t16 & 3) << 3;

    __syncwarp();

    // ---- cache own Y tile in registers (needed by every Horner epilogue) ----
    float yt[8][8];
    #pragma unroll
    for (int r = 0; r < 8; r++) {
        float4 y0 = *(const float4*)(B1 + (r0 + r) * LDM + cT);
        float4 y1 = *(const float4*)(B1 + (r0 + r) * LDM + cT + 4);
        yt[r][0] = y0.x; yt[r][1] = y0.y; yt[r][2] = y0.z; yt[r][3] = y0.w;
        yt[r][4] = y1.x; yt[r][5] = y1.y; yt[r][6] = y1.z; yt[r][7] = y1.w;
    }

    // ---- GEMM 1: W = Y*Y -> B2 ; then B1 <- Acc = a8 I + a9 Y (in place) ----
    {
        float t[8][8] = {};
        gemm8x8(B1, B1, r0, cT, t);
        __syncwarp();   // everyone done reading Y from B1
        const float k0 = CF.a[8], k1 = CF.a[9];
        #pragma unroll
        for (int r = 0; r < 8; r++) {
            int gr = r0 + r;
            *(float4*)(B2 + gr * LDM + cT)     = make_float4(t[r][0], t[r][1], t[r][2], t[r][3]);
            *(float4*)(B2 + gr * LDM + cT + 4) = make_float4(t[r][4], t[r][5], t[r][6], t[r][7]);
            float v[8];
            #pragma unroll
            for (int c = 0; c < 8; c++) v[c] = k1 * yt[r][c];
            int dc = gr - cT;
            if (dc >= 0 && dc < 8) v[dc] += k0;
            *(float4*)(B1 + gr * LDM + cT)     = make_float4(v[0], v[1], v[2], v[3]);
            *(float4*)(B1 + gr * LDM + cT + 4) = make_float4(v[4], v[5], v[6], v[7]);
        }
    }
    __syncwarp();

    // ---- Horner in W: Acc = Acc*W + (a_{2a} I + a_{2a+1} Y), a = 3..0 ----
    #pragma unroll 1
    for (int a = 3; a >= 0; a--) {
        const float k0 = CF.a[2 * a];
        const float k1 = CF.a[2 * a + 1];

        float t[8][8] = {};
        gemm8x8(B1, B2, r0, cT, t);     // Acc * W
        __syncwarp();                   // all reads of Acc done before overwrite

        #pragma unroll
        for (int r = 0; r < 8; r++) {
            int gr = r0 + r;
            float v[8];
            #pragma unroll
            for (int c = 0; c < 8; c++) v[c] = fmaf(k1, yt[r][c], t[r][c]);
            int dc = gr - cT;
            if (dc >= 0 && dc < 8) v[dc] += k0;
            *(float4*)(B1 + gr * LDM + cT)     = make_float4(v[0], v[1], v[2], v[3]);
            *(float4*)(B1 + gr * LDM + cT + 4) = make_float4(v[4], v[5], v[6], v[7]);
        }
        __syncwarp();
    }
    // B1 = log(X)

    // ---- MaxPool2d(4, stride 2): 32x32 -> 15x15 into B2 (W dead) ----
    float* P = B2;
    for (int p = t16; p < NP * NP; p += 16) {
        int pi = p / NP, pj = p - pi * NP;
        float mx = -1e30f;
        #pragma unroll
        for (int a = 0; a < 4; a++)
            #pragma unroll
            for (int b = 0; b < 4; b++)
                mx = fmaxf(mx, B1[(2 * pi + a) * LDM + (2 * pj + b)]);
        P[pi * LDP + pj] = mx;
    }
    __syncwarp();

    // ---- trace shift: mu = tr(P)/15 ----
    if (t16 == 0) {
        float s = 0.f;
        #pragma unroll
        for (int i = 0; i < NP; i++) s += P[i * LDP + i];
        smu[ml] = s * (1.0f / (float)NP);
    }
    __syncwarp();
    const float mu = smu[ml];
    if (t16 < NP) P[t16 * LDP + t16] -= mu;
    __syncwarp();

    // ---- ||P - mu I||_inf ----
    if (t16 < NP) {
        float acc = 0.f;
        #pragma unroll
        for (int j = 0; j < NP; j++) acc += fabsf(P[t16 * LDP + j]);
        norms[ml][t16] = acc;
    }
    __syncwarp();
    if (t16 == 0) {
        float m = 0.f;
        #pragma unroll
        for (int i = 0; i < NP; i++) m = fmaxf(m, norms[ml][i]);
        snrm[ml] = m;
    }
    __syncwarp();
    const float smax = fmaxf(snrm[0], snrm[1]);   // warp-uniform

    int sexp = 0;
    {
        float t = smax;
        while (t > 0.25f && sexp < 40) { t *= 0.5f; sexp++; }
    }
    const float sc = ldexpf(1.0f, -sexp);

    // ---- row-parallel exp: thread i owns row i; P-row cached in regs ----
    // Ec/Eo inside B2 after P; +12 per ml => half-warp offsets 16 mod 32.
    float* EcA = B2sh + ml * MATSZ + 256 + ml * 12;
    float* EoA = B2sh + ml * MATSZ + 512 + ml * 12;

    float prow[16];
    float erow[16];
    if (t16 < NP) {
        float4* pr = (float4*)prow;
        pr[0] = *(const float4*)(P + t16 * LDP);
        pr[1] = *(const float4*)(P + t16 * LDP + 4);
        pr[2] = *(const float4*)(P + t16 * LDP + 8);
        pr[3] = *(const float4*)(P + t16 * LDP + 12);
        #pragma unroll
        for (int j = 0; j < 16; j++) prow[j] *= sc;
        const float it0 = 1.0f / (float)TAYD;
        #pragma unroll
        for (int j = 0; j < 16; j++) erow[j] = prow[j] * it0 + ((j == t16) ? 1.0f : 0.0f);
        float4* er = (float4*)erow;
        *(float4*)(EcA + t16 * LDP)      = er[0];
        *(float4*)(EcA + t16 * LDP + 4)  = er[1];
        *(float4*)(EcA + t16 * LDP + 8)  = er[2];
        *(float4*)(EcA + t16 * LDP + 12) = er[3];
    }
    __syncwarp();

    // Taylor Horner: E <- I + (M*E)/d, d = TAYD-1 .. 1
    #pragma unroll 1
    for (int d = TAYD - 1; d >= 1; d--) {
        const float invd = 1.0f / (float)d;
        if (t16 < NP) {
            float acc[16];
            #pragma unroll
            for (int j = 0; j < 16; j++) acc[j] = 0.f;
            #pragma unroll
            for (int k = 0; k < NP; k++) {
                const float* ek = EcA + k * LDP;
                float4 e0 = *(const float4*)(ek);
                float4 e1 = *(const float4*)(ek + 4);
                float4 e2 = *(const float4*)(ek + 8);
                float4 e3 = *(const float4*)(ek + 12);
                float ev[16] = {e0.x, e0.y, e0.z, e0.w, e1.x, e1.y, e1.z, e1.w,
                                e2.x, e2.y, e2.z, e2.w, e3.x, e3.y, e3.z, e3.w};
                float pk = prow[k];
                #pragma unroll
                for (int j = 0; j < 15; j++) acc[j] = fmaf(pk, ev[j], acc[j]);
            }
            #pragma unroll
            for (int j = 0; j < 16; j++)
                erow[j] = fmaf(acc[j], invd, (j == t16) ? 1.0f : 0.0f);
            float4* er = (float4*)erow;
            *(float4*)(EoA + t16 * LDP)      = er[0];
            *(float4*)(EoA + t16 * LDP + 4)  = er[1];
            *(float4*)(EoA + t16 * LDP + 8)  = er[2];
            *(float4*)(EoA + t16 * LDP + 12) = er[3];
        }
        __syncwarp();
        float* tmp = EcA; EcA = EoA; EoA = tmp;
    }

    // repeated squaring: E <- E*E
    #pragma unroll 1
    for (int q = 0; q < sexp; q++) {
        if (t16 < NP) {
            float acc[16];
            #pragma unroll
            for (int j = 0; j < 16; j++) acc[j] = 0.f;
            #pragma unroll
            for (int k = 0; k < NP; k++) {
                const float* ek = EcA + k * LDP;
                float4 e0 = *(const float4*)(ek);
                float4 e1 = *(const float4*)(ek + 4);
                float4 e2 = *(const float4*)(ek + 8);
                float4 e3 = *(const float4*)(ek + 12);
                float ev[16] = {e0.x, e0.y, e0.z, e0.w, e1.x, e1.y, e1.z, e1.w,
                                e2.x, e2.y, e2.z, e2.w, e3.x, e3.y, e3.z, e3.w};
                float ak = erow[k];
                #pragma unroll
                for (int j = 0; j < 15; j++) acc[j] = fmaf(ak, ev[j], acc[j]);
            }
            #pragma unroll
            for (int j = 0; j < 16; j++) erow[j] = acc[j];
            float4* er = (float4*)erow;
            *(float4*)(EoA + t16 * LDP)      = er[0];
            *(float4*)(EoA + t16 * LDP + 4)  = er[1];
            *(float4*)(EoA + t16 * LDP + 8)  = er[2];
            *(float4*)(EoA + t16 * LDP + 12) = er[3];
        }
        __syncwarp();
        float* tmp = EcA; EcA = EoA; EoA = tmp;
    }

    // ---- output: e^mu * E, straight from registers ----
    if (t16 < NP) {
        const float emu = expf(mu);
        float* orow = yout + mat * (NP * NP) + t16 * NP;
        #pragma unroll
        for (int j = 0; j < NP; j++) orow[j] = emu * erow[j];
    }
}

extern "C" void kernel_launch(void* const* d_in, const int* in_sizes, int n_in,
                              void* d_out, int out_size)
{
    const float* x = (const float*)d_in[0];
    float* out = (float*)d_out;
    const int nmat = in_sizes[0] / (NMM * NMM);   // 32768

    // ---- host: degree-9 Chebyshev coefs of log on [1.0, 7.0] -> monomial in Y ----
    const double m = 4.0, h = 3.0;
    const double r = h / m;
    const double z = (1.0 - sqrt(1.0 - r * r)) / r;
    double c[10];
    c[0] = log(m) - log(1.0 + z * z);
    {
        double zp = 1.0;
        for (int k = 1; k < 10; k++) { zp *= z; c[k] = ((k & 1) ? 2.0 : -2.0) * zp / (double)k; }
    }
    double Tm2[10] = {0}, Tm1[10] = {0}, acc[10] = {0};
    Tm2[0] = 1.0; Tm1[1] = 1.0;
    acc[0] += c[0]; acc[1] += c[1];
    for (int k = 2; k < 10; k++) {
        double Tk[10] = {0};
        for (int j = 0; j < 9; j++) Tk[j + 1] += 2.0 * Tm1[j];
        for (int j = 0; j < 10; j++) Tk[j] -= Tm2[j];
        for (int j = 0; j < 10; j++) acc[j] += c[k] * Tk[j];
        for (int j = 0; j < 10; j++) { Tm2[j] = Tm1[j]; Tm1[j] = Tk[j]; }
    }
    Coefs cf;
    for (int j = 0; j < 10; j++) cf.a[j] = (float)acc[j];

    spd_log_pool_exp<<<nmat / MPB, 32>>>(x, out, cf);
}

// round 9
// speedup vs baseline: 2.9755x; 1.0199x over previous
#include <cuda_runtime.h>
#include <math.h>

// Fused LogEig -> MaxPool(4,2) -> ExpEig for batched 32x32 SPD matrices.
//
// LogEig: degree-7 Chebyshev approximant of log on [1.0, 7.0], converted on
// the host to monomial coefficients, evaluated Paterson-Stockmeyer in W = Y^2:
//   P(Y) = (a0+a1 Y) + W(a2+a3 Y) + W^2(a4+a5 Y) + W^3(a6+a7 Y)
// => 4 GEMMs total (W, then 3 Horner steps).
// Each thread caches its own 8x8 Y-tile in registers so the Y smem buffer is
// reused in-place as the Horner accumulator => two 32x36 buffers, 18.7KB/block.
// __launch_bounds__(32,12) caps regs ~168 => 3 warps/SMSP and 12 blocks/SM.
// ExpEig: trace-shift + scaling-and-squaring + degree-6 Taylor, row-parallel.

#define NMM 32
#define LDM 36
#define MATSZ (NMM * LDM + 4)
#define NP  15
#define LDP 16
#define MPB 2
#define TAYD 6

struct Coefs { float a[8]; };

// t += A * B for symmetric A (row kk read as column kk)
__device__ __forceinline__ void gemm8x8(const float* __restrict__ A,
                                        const float* __restrict__ B,
                                        int r0, int c0, float t[8][8])
{
    #pragma unroll 8
    for (int kk = 0; kk < NMM; kk++) {
        const float* ar = A + kk * LDM;
        const float* br = B + kk * LDM;
        float4 a0 = *(const float4*)(ar + r0);
        float4 a1 = *(const float4*)(ar + r0 + 4);
        float4 b0 = *(const float4*)(br + c0);
        float4 b1 = *(const float4*)(br + c0 + 4);
        float aa[8] = {a0.x, a0.y, a0.z, a0.w, a1.x, a1.y, a1.z, a1.w};
        float bb[8] = {b0.x, b0.y, b0.z, b0.w, b1.x, b1.y, b1.z, b1.w};
        #pragma unroll
        for (int r = 0; r < 8; r++)
            #pragma unroll
            for (int c = 0; c < 8; c++)
                t[r][c] = fmaf(aa[r], bb[c], t[r][c]);
    }
}

__global__ __launch_bounds__(32, 12)
void spd_log_pool_exp(const float* __restrict__ xin, float* __restrict__ yout,
                      const Coefs CF)
{
    __shared__ __align__(16) float B1sh[MPB * MATSZ];  // Y -> Acc -> log(X)
    __shared__ __align__(16) float B2sh[MPB * MATSZ];  // W  -> P / Ec / Eo
    __shared__ float snrm[MPB];
    __shared__ float smu[MPB];

    const int tid = threadIdx.x;
    const int ml  = tid >> 4;
    const int t16 = tid & 15;
    const size_t mat = (size_t)blockIdx.x * MPB + ml;

    float* B1 = B1sh + ml * MATSZ;
    float* B2 = B2sh + ml * MATSZ;

    const float mC   = 4.0f;          // interval [1.0, 7.0]
    const float invh = 1.0f / 3.0f;

    // ---- load X; Y = (X - mI)/h into B1 ----
    {
        const float4* Xv = (const float4*)(xin + mat * (NMM * NMM));
        #pragma unroll
        for (int q = 0; q < 16; q++) {
            int f  = t16 + 16 * q;
            int i  = f >> 3;
            int jb = (f & 7) << 2;
            float4 v = Xv[f];
            float4 yv;
            yv.x = (v.x - ((i == jb + 0) ? mC : 0.f)) * invh;
            yv.y = (v.y - ((i == jb + 1) ? mC : 0.f)) * invh;
            yv.z = (v.z - ((i == jb + 2) ? mC : 0.f)) * invh;
            yv.w = (v.w - ((i == jb + 3) ? mC : 0.f)) * invh;
            *(float4*)(B1 + i * LDM + jb) = yv;
        }
    }

    const int r0 = (t16 >> 2) << 3;
    const int cT = (t16 & 3) << 3;

    __syncwarp();

    // ---- cache own Y tile in registers ----
    float yt[8][8];
    #pragma unroll
    for (int r = 0; r < 8; r++) {
        float4 y0 = *(const float4*)(B1 + (r0 + r) * LDM + cT);
        float4 y1 = *(const float4*)(B1 + (r0 + r) * LDM + cT + 4);
        yt[r][0] = y0.x; yt[r][1] = y0.y; yt[r][2] = y0.z; yt[r][3] = y0.w;
        yt[r][4] = y1.x; yt[r][5] = y1.y; yt[r][6] = y1.z; yt[r][7] = y1.w;
    }

    // ---- GEMM 1: W = Y*Y -> B2 ; then B1 <- Acc = a6 I + a7 Y (in place) ----
    {
        float t[8][8] = {};
        gemm8x8(B1, B1, r0, cT, t);
        __syncwarp();   // everyone done reading Y from B1
        const float k0 = CF.a[6], k1 = CF.a[7];
        #pragma unroll
        for (int r = 0; r < 8; r++) {
            int gr = r0 + r;
            *(float4*)(B2 + gr * LDM + cT)     = make_float4(t[r][0], t[r][1], t[r][2], t[r][3]);
            *(float4*)(B2 + gr * LDM + cT + 4) = make_float4(t[r][4], t[r][5], t[r][6], t[r][7]);
            float v[8];
            #pragma unroll
            for (int c = 0; c < 8; c++) v[c] = k1 * yt[r][c];
            int dc = gr - cT;
            if (dc >= 0 && dc < 8) v[dc] += k0;
            *(float4*)(B1 + gr * LDM + cT)     = make_float4(v[0], v[1], v[2], v[3]);
            *(float4*)(B1 + gr * LDM + cT + 4) = make_float4(v[4], v[5], v[6], v[7]);
        }
    }
    __syncwarp();

    // ---- Horner in W: Acc = Acc*W + (a_{2a} I + a_{2a+1} Y), a = 2,1,0 ----
    #pragma unroll
    for (int a = 2; a >= 0; a--) {
        const float k0 = CF.a[2 * a];
        const float k1 = CF.a[2 * a + 1];

        float t[8][8] = {};
        gemm8x8(B1, B2, r0, cT, t);     // Acc * W
        __syncwarp();                   // all reads of Acc done before overwrite

        #pragma unroll
        for (int r = 0; r < 8; r++) {
            int gr = r0 + r;
            float v[8];
            #pragma unroll
            for (int c = 0; c < 8; c++) v[c] = fmaf(k1, yt[r][c], t[r][c]);
            int dc = gr - cT;
            if (dc >= 0 && dc < 8) v[dc] += k0;
            *(float4*)(B1 + gr * LDM + cT)     = make_float4(v[0], v[1], v[2], v[3]);
            *(float4*)(B1 + gr * LDM + cT + 4) = make_float4(v[4], v[5], v[6], v[7]);
        }
        __syncwarp();
    }
    // B1 = log(X)

    // ---- MaxPool2d(4, stride 2): 32x32 -> 15x15 into B2 (W dead) ----
    float* P = B2;
    for (int p = t16; p < NP * NP; p += 16) {
        int pi = p / NP, pj = p - pi * NP;
        float mx = -1e30f;
        #pragma unroll
        for (int a = 0; a < 4; a++)
            #pragma unroll
            for (int b = 0; b < 4; b++)
                mx = fmaxf(mx, B1[(2 * pi + a) * LDM + (2 * pj + b)]);
        P[pi * LDP + pj] = mx;
    }
    __syncwarp();

    // ---- trace shift: mu = tr(P)/15 ----
    if (t16 == 0) {
        float s = 0.f;
        #pragma unroll
        for (int i = 0; i < NP; i++) s += P[i * LDP + i];
        smu[ml] = s * (1.0f / (float)NP);
    }
    __syncwarp();
    const float mu = smu[ml];
    if (t16 < NP) P[t16 * LDP + t16] -= mu;
    __syncwarp();

    // ---- ||P - mu I||_inf via shfl reduction ----
    {
        float acc = 0.f;
        if (t16 < NP) {
            #pragma unroll
            for (int j = 0; j < NP; j++) acc += fabsf(P[t16 * LDP + j]);
        }
        #pragma unroll
        for (int o = 8; o >= 1; o >>= 1)
            acc = fmaxf(acc, __shfl_xor_sync(0xFFFFFFFFu, acc, o));
        if (t16 == 0) snrm[ml] = acc;
    }
    __syncwarp();
    const float smax = fmaxf(snrm[0], snrm[1]);   // warp-uniform

    int sexp = 0;
    {
        float t = smax;
        while (t > 0.25f && sexp < 40) { t *= 0.5f; sexp++; }
    }
    const float sc = ldexpf(1.0f, -sexp);

    // ---- row-parallel exp: thread i owns row i ----
    float* EcA = B2sh + ml * MATSZ + 256 + ml * 12;
    float* EoA = B2sh + ml * MATSZ + 512 + ml * 12;

    float prow[16];
    float erow[16];
    if (t16 < NP) {
        float4* pr = (float4*)prow;
        pr[0] = *(const float4*)(P + t16 * LDP);
        pr[1] = *(const float4*)(P + t16 * LDP + 4);
        pr[2] = *(const float4*)(P + t16 * LDP + 8);
        pr[3] = *(const float4*)(P + t16 * LDP + 12);
        #pragma unroll
        for (int j = 0; j < 16; j++) prow[j] *= sc;
        const float it0 = 1.0f / (float)TAYD;
        #pragma unroll
        for (int j = 0; j < 16; j++) erow[j] = prow[j] * it0 + ((j == t16) ? 1.0f : 0.0f);
        float4* er = (float4*)erow;
        *(float4*)(EcA + t16 * LDP)      = er[0];
        *(float4*)(EcA + t16 * LDP + 4)  = er[1];
        *(float4*)(EcA + t16 * LDP + 8)  = er[2];
        *(float4*)(EcA + t16 * LDP + 12) = er[3];
    }
    __syncwarp();

    // Taylor Horner: E <- I + (M*E)/d, d = TAYD-1 .. 1
    #pragma unroll 1
    for (int d = TAYD - 1; d >= 1; d--) {
        const float invd = 1.0f / (float)d;
        if (t16 < NP) {
            float acc[16];
            #pragma unroll
            for (int j = 0; j < 16; j++) acc[j] = 0.f;
            #pragma unroll
            for (int k = 0; k < NP; k++) {
                const float* ek = EcA + k * LDP;
                float4 e0 = *(const float4*)(ek);
                float4 e1 = *(const float4*)(ek + 4);
                float4 e2 = *(const float4*)(ek + 8);
                float4 e3 = *(const float4*)(ek + 12);
                float ev[16] = {e0.x, e0.y, e0.z, e0.w, e1.x, e1.y, e1.z, e1.w,
                                e2.x, e2.y, e2.z, e2.w, e3.x, e3.y, e3.z, e3.w};
                float pk = prow[k];
                #pragma unroll
                for (int j = 0; j < 15; j++) acc[j] = fmaf(pk, ev[j], acc[j]);
            }
            #pragma unroll
            for (int j = 0; j < 16; j++)
                erow[j] = fmaf(acc[j], invd, (j == t16) ? 1.0f : 0.0f);
            float4* er = (float4*)erow;
            *(float4*)(EoA + t16 * LDP)      = er[0];
            *(float4*)(EoA + t16 * LDP + 4)  = er[1];
            *(float4*)(EoA + t16 * LDP + 8)  = er[2];
            *(float4*)(EoA + t16 * LDP + 12) = er[3];
        }
        __syncwarp();
        float* tmp = EcA; EcA = EoA; EoA = tmp;
    }

    // repeated squaring: E <- E*E
    #pragma unroll 1
    for (int q = 0; q < sexp; q++) {
        if (t16 < NP) {
            float acc[16];
            #pragma unroll
            for (int j = 0; j < 16; j++) acc[j] = 0.f;
            #pragma unroll
            for (int k = 0; k < NP; k++) {
                const float* ek = EcA + k * LDP;
                float4 e0 = *(const float4*)(ek);
                float4 e1 = *(const float4*)(ek + 4);
                float4 e2 = *(const float4*)(ek + 8);
                float4 e3 = *(const float4*)(ek + 12);
                float ev[16] = {e0.x, e0.y, e0.z, e0.w, e1.x, e1.y, e1.z, e1.w,
                                e2.x, e2.y, e2.z, e2.w, e3.x, e3.y, e3.z, e3.w};
                float ak = erow[k];
                #pragma unroll
                for (int j = 0; j < 15; j++) acc[j] = fmaf(ak, ev[j], acc[j]);
            }
            #pragma unroll
            for (int j = 0; j < 16; j++) erow[j] = acc[j];
            float4* er = (float4*)erow;
            *(float4*)(EoA + t16 * LDP)      = er[0];
            *(float4*)(EoA + t16 * LDP + 4)  = er[1];
            *(float4*)(EoA + t16 * LDP + 8)  = er[2];
            *(float4*)(EoA + t16 * LDP + 12) = er[3];
        }
        __syncwarp();
        float* tmp = EcA; EcA = EoA; EoA = tmp;
    }

    // ---- output: e^mu * E, straight from registers ----
    if (t16 < NP) {
        const float emu = expf(mu);
        float* orow = yout + mat * (NP * NP) + t16 * NP;
        #pragma unroll
        for (int j = 0; j < NP; j++) orow[j] = emu * erow[j];
    }
}

extern "C" void kernel_launch(void* const* d_in, const int* in_sizes, int n_in,
                              void* d_out, int out_size)
{
    const float* x = (const float*)d_in[0];
    float* out = (float*)d_out;
    const int nmat = in_sizes[0] / (NMM * NMM);   // 32768

    // ---- host: degree-7 Chebyshev coefs of log on [1.0, 7.0] -> monomial in Y ----
    const double m = 4.0, h = 3.0;
    const double r = h / m;
    const double z = (1.0 - sqrt(1.0 - r * r)) / r;
    double c[8];
    c[0] = log(m) - log(1.0 + z * z);
    {
        double zp = 1.0;
        for (int k = 1; k < 8; k++) { zp *= z; c[k] = ((k & 1) ? 2.0 : -2.0) * zp / (double)k; }
    }
    double Tm2[8] = {0}, Tm1[8] = {0}, acc[8] = {0};
    Tm2[0] = 1.0; Tm1[1] = 1.0;
    acc[0] += c[0]; acc[1] += c[1];
    for (int k = 2; k < 8; k++) {
        double Tk[8] = {0};
        for (int j = 0; j < 7; j++) Tk[j + 1] += 2.0 * Tm1[j];
        for (int j = 0; j < 8; j++) Tk[j] -= Tm2[j];
        for (int j = 0; j < 8; j++) acc[j] += c[k] * Tk[j];
        for (int j = 0; j < 8; j++) { Tm2[j] = Tm1[j]; Tm1[j] = Tk[j]; }
    }
    Coefs cf;
    for (int j = 0; j < 8; j++) cf.a[j] = (float)acc[j];

    spd_log_pool_exp<<<nmat / MPB, 32>>>(x, out, cf);
}

// round 10
// speedup vs baseline: 3.1091x; 1.0449x over previous
#include <cuda_runtime.h>
#include <math.h>

// Fused LogEig -> MaxPool(4,2) -> ExpEig for batched 32x32 SPD matrices.
//
// LogEig: degree-7 Chebyshev approximant of log on [1.0, 7.0] -> monomial,
// Paterson-Stockmeyer in W = Y^2: 4 GEMMs (W + 3 Horner steps), 8x8 tiles.
// ExpEig: trace-shift + scaling-and-squaring + degree-6 Taylor; the 15x15
// matrix is zero-padded to 16x16 and every multiply is a 4x4-register-tile
// GEMM (symmetric operands -> rows read as columns), so exp loads are plain
// float4 streams instead of register-array broadcasts (no spills, fewer wf).
//
// 2 matrices / 32-thread block, 16 threads / matrix. Per-matrix buffers are
// staggered so the two half-warps hit disjoint shared-memory bank sets.

#define NMM 32
#define LDM 36
#define MATSZ (NMM * LDM + 4)
#define NP  15
#define LDP 16
#define MPB 2
#define TAYD 6

struct Coefs { float a[8]; };

// t += A * B for symmetric A (row kk read as column kk), 8x8 tile
__device__ __forceinline__ void gemm8x8(const float* __restrict__ A,
                                        const float* __restrict__ B,
                                        int r0, int c0, float t[8][8])
{
    #pragma unroll 8
    for (int kk = 0; kk < NMM; kk++) {
        const float* ar = A + kk * LDM;
        const float* br = B + kk * LDM;
        float4 a0 = *(const float4*)(ar + r0);
        float4 a1 = *(const float4*)(ar + r0 + 4);
        float4 b0 = *(const float4*)(br + c0);
        float4 b1 = *(const float4*)(br + c0 + 4);
        float aa[8] = {a0.x, a0.y, a0.z, a0.w, a1.x, a1.y, a1.z, a1.w};
        float bb[8] = {b0.x, b0.y, b0.z, b0.w, b1.x, b1.y, b1.z, b1.w};
        #pragma unroll
        for (int r = 0; r < 8; r++)
            #pragma unroll
            for (int c = 0; c < 8; c++)
                t[r][c] = fmaf(aa[r], bb[c], t[r][c]);
    }
}

__global__ __launch_bounds__(32, 12)
void spd_log_pool_exp(const float* __restrict__ xin, float* __restrict__ yout,
                      const Coefs CF)
{
    __shared__ __align__(16) float B1sh[MPB * MATSZ];  // Y -> Acc -> log(X)
    __shared__ __align__(16) float B2sh[MPB * MATSZ];  // W  -> P / E1 / E2
    __shared__ float snrm[MPB];
    __shared__ float smu[MPB];

    const int tid = threadIdx.x;
    const int ml  = tid >> 4;
    const int t16 = tid & 15;
    const size_t mat = (size_t)blockIdx.x * MPB + ml;

    float* B1 = B1sh + ml * MATSZ;
    float* B2 = B2sh + ml * MATSZ;

    const float mC   = 4.0f;          // interval [1.0, 7.0]
    const float invh = 1.0f / 3.0f;

    // ---- load X; Y = (X - mI)/h into B1 ----
    {
        const float4* Xv = (const float4*)(xin + mat * (NMM * NMM));
        #pragma unroll
        for (int q = 0; q < 16; q++) {
            int f  = t16 + 16 * q;
            int i  = f >> 3;
            int jb = (f & 7) << 2;
            float4 v = Xv[f];
            float4 yv;
            yv.x = (v.x - ((i == jb + 0) ? mC : 0.f)) * invh;
            yv.y = (v.y - ((i == jb + 1) ? mC : 0.f)) * invh;
            yv.z = (v.z - ((i == jb + 2) ? mC : 0.f)) * invh;
            yv.w = (v.w - ((i == jb + 3) ? mC : 0.f)) * invh;
            *(float4*)(B1 + i * LDM + jb) = yv;
        }
    }

    const int r0 = (t16 >> 2) << 3;
    const int cT = (t16 & 3) << 3;

    __syncwarp();

    // ---- cache own Y tile in registers ----
    float yt[8][8];
    #pragma unroll
    for (int r = 0; r < 8; r++) {
        float4 y0 = *(const float4*)(B1 + (r0 + r) * LDM + cT);
        float4 y1 = *(const float4*)(B1 + (r0 + r) * LDM + cT + 4);
        yt[r][0] = y0.x; yt[r][1] = y0.y; yt[r][2] = y0.z; yt[r][3] = y0.w;
        yt[r][4] = y1.x; yt[r][5] = y1.y; yt[r][6] = y1.z; yt[r][7] = y1.w;
    }

    // ---- GEMM 1: W = Y*Y -> B2 ; B1 <- Acc = a6 I + a7 Y (in place) ----
    {
        float t[8][8] = {};
        gemm8x8(B1, B1, r0, cT, t);
        __syncwarp();
        const float k0 = CF.a[6], k1 = CF.a[7];
        #pragma unroll
        for (int r = 0; r < 8; r++) {
            int gr = r0 + r;
            *(float4*)(B2 + gr * LDM + cT)     = make_float4(t[r][0], t[r][1], t[r][2], t[r][3]);
            *(float4*)(B2 + gr * LDM + cT + 4) = make_float4(t[r][4], t[r][5], t[r][6], t[r][7]);
            float v[8];
            #pragma unroll
            for (int c = 0; c < 8; c++) v[c] = k1 * yt[r][c];
            int dc = gr - cT;
            if (dc >= 0 && dc < 8) v[dc] += k0;
            *(float4*)(B1 + gr * LDM + cT)     = make_float4(v[0], v[1], v[2], v[3]);
            *(float4*)(B1 + gr * LDM + cT + 4) = make_float4(v[4], v[5], v[6], v[7]);
        }
    }
    __syncwarp();

    // ---- Horner in W: Acc = Acc*W + (a_{2a} I + a_{2a+1} Y), a = 2,1,0 ----
    #pragma unroll
    for (int a = 2; a >= 0; a--) {
        const float k0 = CF.a[2 * a];
        const float k1 = CF.a[2 * a + 1];

        float t[8][8] = {};
        gemm8x8(B1, B2, r0, cT, t);
        __syncwarp();

        #pragma unroll
        for (int r = 0; r < 8; r++) {
            int gr = r0 + r;
            float v[8];
            #pragma unroll
            for (int c = 0; c < 8; c++) v[c] = fmaf(k1, yt[r][c], t[r][c]);
            int dc = gr - cT;
            if (dc >= 0 && dc < 8) v[dc] += k0;
            *(float4*)(B1 + gr * LDM + cT)     = make_float4(v[0], v[1], v[2], v[3]);
            *(float4*)(B1 + gr * LDM + cT + 4) = make_float4(v[4], v[5], v[6], v[7]);
        }
        __syncwarp();
    }
    // B1 = log(X)

    // ---- exp workspace inside B2 (W dead). Staggered so half-warps are
    // 16 banks apart: per-ml offset = MATSZ + 12 == 16 (mod 32) floats.
    float* Pp = B2sh + ml * (MATSZ + 12);        // 16x16 padded pooled matrix
    float* E1 = Pp + 384;
    float* E2 = Pp + 768;

    // zero the 16x16 pad
    for (int p = t16; p < 256; p += 16) Pp[p] = 0.f;
    __syncwarp();

    // ---- MaxPool2d(4, stride 2): 32x32 -> 15x15 into Pp ----
    for (int p = t16; p < NP * NP; p += 16) {
        int pi = p / NP, pj = p - pi * NP;
        float mx = -1e30f;
        #pragma unroll
        for (int a = 0; a < 4; a++)
            #pragma unroll
            for (int b = 0; b < 4; b++)
                mx = fmaxf(mx, B1[(2 * pi + a) * LDM + (2 * pj + b)]);
        Pp[pi * LDP + pj] = mx;
    }
    __syncwarp();

    // ---- trace shift: mu = tr(P)/15 ----
    if (t16 == 0) {
        float s = 0.f;
        #pragma unroll
        for (int i = 0; i < NP; i++) s += Pp[i * LDP + i];
        smu[ml] = s * (1.0f / (float)NP);
    }
    __syncwarp();
    const float mu = smu[ml];
    if (t16 < NP) Pp[t16 * LDP + t16] -= mu;
    __syncwarp();

    // ---- ||P - mu I||_inf via shfl ----
    {
        float acc = 0.f;
        if (t16 < NP) {
            #pragma unroll
            for (int j = 0; j < NP; j++) acc += fabsf(Pp[t16 * LDP + j]);
        }
        #pragma unroll
        for (int o = 8; o >= 1; o >>= 1)
            acc = fmaxf(acc, __shfl_xor_sync(0xFFFFFFFFu, acc, o));
        if (t16 == 0) snrm[ml] = acc;
    }
    __syncwarp();
    const float smax = fmaxf(snrm[0], snrm[1]);   // warp-uniform

    int sexp = 0;
    {
        float t = smax;
        while (t > 0.25f && sexp < 40) { t *= 0.5f; sexp++; }
    }
    const float sc = ldexpf(1.0f, -sexp);

    // scale M and build E1 = I + M/TAYD in one pass
    {
        const float it0 = 1.0f / (float)TAYD;
        for (int p = t16; p < 256; p += 16) {
            float mv = Pp[p] * sc;
            Pp[p] = mv;
            int pi = p >> 4, pj = p & 15;
            E1[p] = mv * it0 + ((pi == pj) ? 1.0f : 0.0f);
        }
    }
    __syncwarp();

    // ---- exp via 4x4-tile GEMMs on padded 16x16 ----
    const int er0 = (t16 >> 2) << 2;
    const int ec0 = (t16 & 3) << 2;
    float* Ec = E1;
    float* Eo = E2;

    // Taylor Horner: E <- I + (M*E)/d, d = TAYD-1 .. 1
    #pragma unroll 1
    for (int d = TAYD - 1; d >= 1; d--) {
        const float invd = 1.0f / (float)d;
        float t[4][4] = {};
        #pragma unroll
        for (int k = 0; k < 16; k++) {
            float4 av = *(const float4*)(Pp + k * LDP + er0);  // M sym: row as col
            float4 bv = *(const float4*)(Ec + k * LDP + ec0);
            float aa[4] = {av.x, av.y, av.z, av.w};
            float bb[4] = {bv.x, bv.y, bv.z, bv.w};
            #pragma unroll
            for (int r = 0; r < 4; r++)
                #pragma unroll
                for (int c = 0; c < 4; c++)
                    t[r][c] = fmaf(aa[r], bb[c], t[r][c]);
        }
        #pragma unroll
        for (int r = 0; r < 4; r++) {
            int gr = er0 + r;
            float v[4];
            #pragma unroll
            for (int c = 0; c < 4; c++)
                v[c] = fmaf(t[r][c], invd, (gr == ec0 + c) ? 1.0f : 0.0f);
            *(float4*)(Eo + gr * LDP + ec0) = make_float4(v[0], v[1], v[2], v[3]);
        }
        __syncwarp();
        float* tmp = Ec; Ec = Eo; Eo = tmp;
    }

    // repeated squaring: E <- E*E (E symmetric)
    #pragma unroll 1
    for (int q = 0; q < sexp; q++) {
        float t[4][4] = {};
        #pragma unroll
        for (int k = 0; k < 16; k++) {
            float4 av = *(const float4*)(Ec + k * LDP + er0);
            float4 bv = *(const float4*)(Ec + k * LDP + ec0);
            float aa[4] = {av.x, av.y, av.z, av.w};
            float bb[4] = {bv.x, bv.y, bv.z, bv.w};
            #pragma unroll
            for (int r = 0; r < 4; r++)
                #pragma unroll
                for (int c = 0; c < 4; c++)
                    t[r][c] = fmaf(aa[r], bb[c], t[r][c]);
        }
        __syncwarp();   // reads done before overwrite? (writes go to Eo; sync
                        // protects next iter's reads) -- keep before store swap
        #pragma unroll
        for (int r = 0; r < 4; r++)
            *(float4*)(Eo + (er0 + r) * LDP + ec0) =
                make_float4(t[r][0], t[r][1], t[r][2], t[r][3]);
        __syncwarp();
        float* tmp = Ec; Ec = Eo; Eo = tmp;
    }

    // ---- output: e^mu * E (15x15 block) ----
    if (t16 < NP) {
        const float emu = expf(mu);
        const float* erow = Ec + t16 * LDP;
        float* orow = yout + mat * (NP * NP) + t16 * NP;
        #pragma unroll
        for (int j = 0; j < NP; j++) orow[j] = emu * erow[j];
    }
}

extern "C" void kernel_launch(void* const* d_in, const int* in_sizes, int n_in,
                              void* d_out, int out_size)
{
    const float* x = (const float*)d_in[0];
    float* out = (float*)d_out;
    const int nmat = in_sizes[0] / (NMM * NMM);   // 32768

    // ---- host: degree-7 Chebyshev coefs of log on [1.0, 7.0] -> monomial ----
    const double m = 4.0, h = 3.0;
    const double r = h / m;
    const double z = (1.0 - sqrt(1.0 - r * r)) / r;
    double c[8];
    c[0] = log(m) - log(1.0 + z * z);
    {
        double zp = 1.0;
        for (int k = 1; k < 8; k++) { zp *= z; c[k] = ((k & 1) ? 2.0 : -2.0) * zp / (double)k; }
    }
    double Tm2[8] = {0}, Tm1[8] = {0}, acc[8] = {0};
    Tm2[0] = 1.0; Tm1[1] = 1.0;
    acc[0] += c[0]; acc[1] += c[1];
    for (int k = 2; k < 8; k++) {
        double Tk[8] = {0};
        for (int j = 0; j < 7; j++) Tk[j + 1] += 2.0 * Tm1[j];
        for (int j = 0; j < 8; j++) Tk[j] -= Tm2[j];
        for (int j = 0; j < 8; j++) acc[j] += c[k] * Tk[j];
        for (int j = 0; j < 8; j++) { Tm2[j] = Tm1[j]; Tm1[j] = Tk[j]; }
    }
    Coefs cf;
    for (int j = 0; j < 8; j++) cf.a[j] = (float)acc[j];

    spd_log_pool_exp<<<nmat / MPB, 32>>>(x, out, cf);
}